// round 2
// baseline (speedup 1.0000x reference)
#include <cuda_runtime.h>

#define BB 256
#define NN 192
#define CC 256
#define GG 8
#define DD 32
#define NP 193   // padded S row (odd -> conflict-free smem)
#define SCALEF 0.17677669529663688f

typedef unsigned long long u64;

// scratch (allocation-free rule: __device__ globals)
__device__ float g_q[BB * NN * DD];   //  6 MB   [b][n][d]
__device__ float g_k[BB * NN * CC];   // 50 MB   [b][n][g][o]

// ---------- packed f32x2 helpers (sm_100+) ----------
__device__ __forceinline__ u64 pack2(float x, float y) {
    u64 r; asm("mov.b64 %0,{%1,%2};" : "=l"(r) : "f"(x), "f"(y)); return r;
}
__device__ __forceinline__ void unpack2(u64 v, float& x, float& y) {
    asm("mov.b64 {%0,%1},%2;" : "=f"(x), "=f"(y) : "l"(v));
}
__device__ __forceinline__ void ffma2(u64& d, u64 a, u64 b) {
    asm("fma.rn.f32x2 %0,%1,%2,%0;" : "+l"(d) : "l"(a), "l"(b));
}

// ============================================================
// q[b,n,d] = sum_c x[b,n,c] * Wq[d,c] + bq[d]
// 8 rows per block, 256 threads: thread = (r, d)
// Wq staged transposed+paired: Wt2[c/2][d] = (Wq[d][c], Wq[d][c+1])
// ============================================================
__global__ void __launch_bounds__(256) proj_q_kernel(
    const float* __restrict__ x, const float* __restrict__ Wq,
    const float* __restrict__ bq)
{
    __shared__ u64 Wt2[128][32];   // 32 KB
    __shared__ u64 xs[8][128];     //  8 KB
    const int tid = threadIdx.x;
    const long row0 = (long)blockIdx.x * 8;

    // stage Wq (transpose into c-major pairs)
    for (int idx = tid; idx < DD * CC; idx += 256) {
        int d = idx >> 8, c = idx & 255;
        ((float*)&Wt2[c >> 1][d])[c & 1] = Wq[idx];
    }
    // stage x rows
    {
        const u64* src = (const u64*)(x + row0 * CC);
        u64* dst = &xs[0][0];
#pragma unroll
        for (int t = 0; t < 4; ++t) dst[tid + t * 256] = src[tid + t * 256];
    }
    __syncthreads();

    const int r = tid >> 5, d = tid & 31;
    u64 acc[4] = {0ull, 0ull, 0ull, 0ull};
    const u64* xp = xs[r];
#pragma unroll 16
    for (int c2 = 0; c2 < 128; ++c2)
        ffma2(acc[c2 & 3], xp[c2], Wt2[c2][d]);

    float s = 0.f;
#pragma unroll
    for (int t = 0; t < 4; ++t) { float lo, hi; unpack2(acc[t], lo, hi); s += lo + hi; }
    g_q[row0 * DD + tid] = s + bq[d];
}

// ============================================================
// k[b,n,g,o] = sum_i x[b,n,g*32+i] * Wk[g,o,i] + bk[g,o]
// 8 rows per block, 256 threads: thread = column (g,o), owns all 8 rows
// x staged transposed (xs_t[c][r], row pairs -> f32x2 along rows)
// ============================================================
__global__ void __launch_bounds__(256) proj_k_kernel(
    const float* __restrict__ x, const float* __restrict__ Wk,
    const float* __restrict__ bk)
{
    __shared__ float Wt[GG][DD][DD + 1];  // [g][i][o], padded: ~33 KB
    __shared__ float xs_t[CC][10];        // [c][r], padded: 10 KB
    const int tid = threadIdx.x;
    const long row0 = (long)blockIdx.x * 8;

    for (int idx = tid; idx < GG * DD * DD; idx += 256) {
        int g = idx >> 10, o = (idx >> 5) & 31, i = idx & 31;
        Wt[g][i][o] = Wk[idx];
    }
    for (int idx = tid; idx < 8 * CC; idx += 256) {
        int r = idx >> 8, c = idx & 255;
        xs_t[c][r] = x[row0 * CC + idx];
    }
    const float bkv = bk[tid];
    __syncthreads();

    const int g = tid >> 5, o = tid & 31;
    const u64 binit = pack2(bkv, bkv);
    u64 acc[4];
#pragma unroll
    for (int t = 0; t < 4; ++t) acc[t] = binit;

#pragma unroll 8
    for (int i = 0; i < 32; ++i) {
        float w = Wt[g][i][o];
        u64 wp = pack2(w, w);
        const u64* xr = (const u64*)&xs_t[g * 32 + i][0];  // (r0,r1)(r2,r3)(r4,r5)(r6,r7)
        ffma2(acc[0], wp, xr[0]);
        ffma2(acc[1], wp, xr[1]);
        ffma2(acc[2], wp, xr[2]);
        ffma2(acc[3], wp, xr[3]);
    }
#pragma unroll
    for (int rp = 0; rp < 4; ++rp) {
        float v0, v1; unpack2(acc[rp], v0, v1);
        g_k[(row0 + 2 * rp    ) * CC + tid] = v0;   // coalesced: col = tid
        g_k[(row0 + 2 * rp + 1) * CC + tid] = v1;
    }
}

// ============================================================
// attention: 1 block per (b,g); 192 threads, 1 thread = 1 query row.
// smem: q(24K) k(24K) v(24K) S[192][193](148K) inv[192] = 222720 B
// ============================================================
__global__ void __launch_bounds__(192, 1) attn_kernel(
    const float* __restrict__ x, float* __restrict__ ctx_out,
    float* __restrict__ attn_out)
{
    extern __shared__ float sm[];
    float* q_s   = sm;
    float* k_s   = q_s + NN * DD;
    float* v_s   = k_s + NN * DD;
    float* S     = v_s + NN * DD;
    float* inv_s = S + NN * NP;

    const int tid = threadIdx.x;
    const int b = blockIdx.x >> 3;
    const int g = blockIdx.x & 7;

    // ---- cooperative loads (float4, fully coalesced, 128B-aligned rows) ----
    {
        const float4* qsrc = (const float4*)(g_q + (size_t)b * NN * DD);
        float4* qdst = (float4*)q_s;
        float4* kdst = (float4*)k_s;
        float4* vdst = (float4*)v_s;
#pragma unroll
        for (int t = 0; t < 8; ++t) {
            int idx = tid + t * 192;
            qdst[idx] = qsrc[idx];
            int n = idx >> 3, f = idx & 7;
            kdst[idx] = ((const float4*)(g_k + ((size_t)(b * NN + n) * GG + g) * DD))[f];
            vdst[idx] = ((const float4*)(x + (size_t)(b * NN + n) * CC + g * DD))[f];
        }
    }
    __syncthreads();

    const int i = tid;  // my row
    u64 qp[16];
    {
        const u64* qr = (const u64*)(q_s + i * DD);
#pragma unroll
        for (int t = 0; t < 16; ++t) qp[t] = qr[t];
    }
    float* Srow = S + i * NP;

    // ---- pass 1: S[i][j] = scale * q_i . k_j ; track row max ----
    float m = -1e30f;
#pragma unroll 2
    for (int j = 0; j < NN; ++j) {
        u64 acc[4] = {0ull, 0ull, 0ull, 0ull};
        const u64* kr = (const u64*)(k_s + j * DD);  // warp-uniform -> broadcast
#pragma unroll
        for (int t = 0; t < 16; ++t) ffma2(acc[t & 3], qp[t], kr[t]);
        float a0, b0, a1, b1, a2, b2, a3, b3;
        unpack2(acc[0], a0, b0); unpack2(acc[1], a1, b1);
        unpack2(acc[2], a2, b2); unpack2(acc[3], a3, b3);
        float s = (((a0 + b0) + (a1 + b1)) + ((a2 + b2) + (a3 + b3))) * SCALEF;
        m = fmaxf(m, s);
        Srow[j] = s;
    }

    // ---- pass 2: exp + row sum (unnormalized e kept in S) ----
    float s0 = 0.f, s1 = 0.f, s2 = 0.f, s3 = 0.f;
#pragma unroll 2
    for (int j = 0; j < NN; j += 4) {
        float e0 = __expf(Srow[j    ] - m);
        float e1 = __expf(Srow[j + 1] - m);
        float e2 = __expf(Srow[j + 2] - m);
        float e3 = __expf(Srow[j + 3] - m);
        Srow[j] = e0; Srow[j + 1] = e1; Srow[j + 2] = e2; Srow[j + 3] = e3;
        s0 += e0; s1 += e1; s2 += e2; s3 += e3;
    }
    const float inv = 1.0f / ((s0 + s1) + (s2 + s3));
    inv_s[i] = inv;

    // ---- pass 3: ctx_i = inv * sum_j e_ij * v_j ----
    u64 acc2[16];
#pragma unroll
    for (int t = 0; t < 16; ++t) acc2[t] = 0ull;
#pragma unroll 2
    for (int j = 0; j < NN; ++j) {
        float a = Srow[j];
        u64 ap = pack2(a, a);
        const u64* vr = (const u64*)(v_s + j * DD);  // warp-uniform -> broadcast
#pragma unroll
        for (int t = 0; t < 16; ++t) ffma2(acc2[t], ap, vr[t]);
    }
    if (ctx_out) {
        float2* cdst = (float2*)(ctx_out + ((size_t)(b * NN + i)) * CC + g * DD);
#pragma unroll
        for (int t = 0; t < 16; ++t) {
            float lo, hi; unpack2(acc2[t], lo, hi);
            cdst[t] = make_float2(lo * inv, hi * inv);
        }
    }
    __syncthreads();

    // ---- pass 4: coalesced attn write: warp covers consecutive j ----
    if (attn_out) {
        float* adst = attn_out + (size_t)blockIdx.x * (NN * NN);
#pragma unroll 4
        for (int row = 0; row < NN; ++row)
            adst[row * NN + tid] = S[row * NP + tid] * inv_s[row];
    }
}

extern "C" void kernel_launch(void* const* d_in, const int* in_sizes, int n_in,
                              void* d_out, int out_size)
{
    const float* x  = (const float*)d_in[0];
    const float* Wq = (const float*)d_in[1];
    const float* bq = (const float*)d_in[2];
    const float* Wk = (const float*)d_in[3];
    const float* bk = (const float*)d_in[4];

    const size_t ctx_elems  = (size_t)BB * NN * CC;          // 12,582,912
    const size_t attn_elems = (size_t)BB * GG * NN * NN;     // 75,497,472

    float* ctx_ptr  = nullptr;
    float* attn_ptr = nullptr;
    const size_t osz = (size_t)out_size;
    if (osz >= ctx_elems + attn_elems) {          // tuple flattened: ctx then attn
        ctx_ptr  = (float*)d_out;
        attn_ptr = (float*)d_out + ctx_elems;
    } else if (osz == attn_elems) {               // attn only
        attn_ptr = (float*)d_out;
    } else {                                      // ctx only
        ctx_ptr = (float*)d_out;
    }

    constexpr int SMEM_BYTES = (NN * DD * 3 + NN * NP + NN) * 4;  // 222720
    cudaFuncSetAttribute(attn_kernel, cudaFuncAttributeMaxDynamicSharedMemorySize,
                         SMEM_BYTES);

    proj_q_kernel<<<BB * NN / 8, 256>>>(x, Wq, bq);
    proj_k_kernel<<<BB * NN / 8, 256>>>(x, Wk, bk);
    attn_kernel<<<BB * GG, 192, SMEM_BYTES>>>(x, ctx_ptr, attn_ptr);
}

// round 3
// speedup vs baseline: 1.0021x; 1.0021x over previous
#include <cuda_runtime.h>

#define BB 256
#define NN 192
#define CC 256
#define GG 8
#define DD 32
#define NP 193   // padded S row (odd -> conflict-free smem)
#define SCALEF 0.17677669529663688f

typedef unsigned long long u64;

// scratch (allocation-free rule: __device__ globals)
__device__ float g_q[BB * NN * DD];   //  6 MB   [b][n][d]
__device__ float g_k[BB * NN * CC];   // 50 MB   [b][n][g][o]

// ---------- packed f32x2 helpers (sm_100+) ----------
__device__ __forceinline__ u64 pack2(float x, float y) {
    u64 r; asm("mov.b64 %0,{%1,%2};" : "=l"(r) : "f"(x), "f"(y)); return r;
}
__device__ __forceinline__ void unpack2(u64 v, float& x, float& y) {
    asm("mov.b64 {%0,%1},%2;" : "=f"(x), "=f"(y) : "l"(v));
}
__device__ __forceinline__ void ffma2(u64& d, u64 a, u64 b) {
    asm("fma.rn.f32x2 %0,%1,%2,%0;" : "+l"(d) : "l"(a), "l"(b));
}

// ============================================================
// q[b,n,d] = sum_c x[b,n,c] * Wq[d,c] + bq[d]
// 8 rows per block, 256 threads: thread = (r, d)
// Wq staged transposed+paired: Wt2[c/2][d] = (Wq[d][c], Wq[d][c+1])
// ============================================================
__global__ void __launch_bounds__(256) proj_q_kernel(
    const float* __restrict__ x, const float* __restrict__ Wq,
    const float* __restrict__ bq)
{
    __shared__ u64 Wt2[128][32];   // 32 KB
    __shared__ u64 xs[8][128];     //  8 KB
    const int tid = threadIdx.x;
    const long row0 = (long)blockIdx.x * 8;

    // stage Wq (transpose into c-major pairs)
    for (int idx = tid; idx < DD * CC; idx += 256) {
        int d = idx >> 8, c = idx & 255;
        ((float*)&Wt2[c >> 1][d])[c & 1] = Wq[idx];
    }
    // stage x rows
    {
        const u64* src = (const u64*)(x + row0 * CC);
        u64* dst = &xs[0][0];
#pragma unroll
        for (int t = 0; t < 4; ++t) dst[tid + t * 256] = src[tid + t * 256];
    }
    __syncthreads();

    const int r = tid >> 5, d = tid & 31;
    u64 acc[4] = {0ull, 0ull, 0ull, 0ull};
    const u64* xp = xs[r];
#pragma unroll 16
    for (int c2 = 0; c2 < 128; ++c2)
        ffma2(acc[c2 & 3], xp[c2], Wt2[c2][d]);

    float s = 0.f;
#pragma unroll
    for (int t = 0; t < 4; ++t) { float lo, hi; unpack2(acc[t], lo, hi); s += lo + hi; }
    g_q[row0 * DD + tid] = s + bq[d];
}

// ============================================================
// k[b,n,g,o] = sum_i x[b,n,g*32+i] * Wk[g,o,i] + bk[g,o]
// 8 rows per block, 256 threads: thread = column (g,o), owns all 8 rows
// x staged transposed (xs_t[c][r], row pairs -> f32x2 along rows)
// ============================================================
__global__ void __launch_bounds__(256) proj_k_kernel(
    const float* __restrict__ x, const float* __restrict__ Wk,
    const float* __restrict__ bk)
{
    __shared__ float Wt[GG][DD][DD + 1];  // [g][i][o], padded: ~33 KB
    __shared__ float xs_t[CC][10];        // [c][r], padded: 10 KB
    const int tid = threadIdx.x;
    const long row0 = (long)blockIdx.x * 8;

    for (int idx = tid; idx < GG * DD * DD; idx += 256) {
        int g = idx >> 10, o = (idx >> 5) & 31, i = idx & 31;
        Wt[g][i][o] = Wk[idx];
    }
    for (int idx = tid; idx < 8 * CC; idx += 256) {
        int r = idx >> 8, c = idx & 255;
        xs_t[c][r] = x[row0 * CC + idx];
    }
    const float bkv = bk[tid];
    __syncthreads();

    const int g = tid >> 5, o = tid & 31;
    const u64 binit = pack2(bkv, bkv);
    u64 acc[4];
#pragma unroll
    for (int t = 0; t < 4; ++t) acc[t] = binit;

#pragma unroll 8
    for (int i = 0; i < 32; ++i) {
        float w = Wt[g][i][o];
        u64 wp = pack2(w, w);
        const u64* xr = (const u64*)&xs_t[g * 32 + i][0];  // (r0,r1)(r2,r3)(r4,r5)(r6,r7)
        ffma2(acc[0], wp, xr[0]);
        ffma2(acc[1], wp, xr[1]);
        ffma2(acc[2], wp, xr[2]);
        ffma2(acc[3], wp, xr[3]);
    }
#pragma unroll
    for (int rp = 0; rp < 4; ++rp) {
        float v0, v1; unpack2(acc[rp], v0, v1);
        g_k[(row0 + 2 * rp    ) * CC + tid] = v0;   // coalesced: col = tid
        g_k[(row0 + 2 * rp + 1) * CC + tid] = v1;
    }
}

// ============================================================
// attention: 1 block per (b,g); 192 threads, 1 thread = 1 query row.
// smem: q(24K) k(24K) v(24K) S[192][193](148K) inv[192] = 222720 B
// ============================================================
__global__ void __launch_bounds__(192, 1) attn_kernel(
    const float* __restrict__ x, float* __restrict__ ctx_out,
    float* __restrict__ attn_out)
{
    extern __shared__ float sm[];
    float* q_s   = sm;
    float* k_s   = q_s + NN * DD;
    float* v_s   = k_s + NN * DD;
    float* S     = v_s + NN * DD;
    float* inv_s = S + NN * NP;

    const int tid = threadIdx.x;
    const int b = blockIdx.x >> 3;
    const int g = blockIdx.x & 7;

    // ---- cooperative loads (float4, fully coalesced, 128B-aligned rows) ----
    {
        const float4* qsrc = (const float4*)(g_q + (size_t)b * NN * DD);
        float4* qdst = (float4*)q_s;
        float4* kdst = (float4*)k_s;
        float4* vdst = (float4*)v_s;
#pragma unroll
        for (int t = 0; t < 8; ++t) {
            int idx = tid + t * 192;
            qdst[idx] = qsrc[idx];
            int n = idx >> 3, f = idx & 7;
            kdst[idx] = ((const float4*)(g_k + ((size_t)(b * NN + n) * GG + g) * DD))[f];
            vdst[idx] = ((const float4*)(x + (size_t)(b * NN + n) * CC + g * DD))[f];
        }
    }
    __syncthreads();

    const int i = tid;  // my row
    u64 qp[16];
    {
        const u64* qr = (const u64*)(q_s + i * DD);
#pragma unroll
        for (int t = 0; t < 16; ++t) qp[t] = qr[t];
    }
    float* Srow = S + i * NP;

    // ---- pass 1: S[i][j] = scale * q_i . k_j ; track row max ----
    float m = -1e30f;
#pragma unroll 2
    for (int j = 0; j < NN; ++j) {
        u64 acc[4] = {0ull, 0ull, 0ull, 0ull};
        const u64* kr = (const u64*)(k_s + j * DD);  // warp-uniform -> broadcast
#pragma unroll
        for (int t = 0; t < 16; ++t) ffma2(acc[t & 3], qp[t], kr[t]);
        float a0, b0, a1, b1, a2, b2, a3, b3;
        unpack2(acc[0], a0, b0); unpack2(acc[1], a1, b1);
        unpack2(acc[2], a2, b2); unpack2(acc[3], a3, b3);
        float s = (((a0 + b0) + (a1 + b1)) + ((a2 + b2) + (a3 + b3))) * SCALEF;
        m = fmaxf(m, s);
        Srow[j] = s;
    }

    // ---- pass 2: exp + row sum (unnormalized e kept in S) ----
    float s0 = 0.f, s1 = 0.f, s2 = 0.f, s3 = 0.f;
#pragma unroll 2
    for (int j = 0; j < NN; j += 4) {
        float e0 = __expf(Srow[j    ] - m);
        float e1 = __expf(Srow[j + 1] - m);
        float e2 = __expf(Srow[j + 2] - m);
        float e3 = __expf(Srow[j + 3] - m);
        Srow[j] = e0; Srow[j + 1] = e1; Srow[j + 2] = e2; Srow[j + 3] = e3;
        s0 += e0; s1 += e1; s2 += e2; s3 += e3;
    }
    const float inv = 1.0f / ((s0 + s1) + (s2 + s3));
    inv_s[i] = inv;

    // ---- pass 3: ctx_i = inv * sum_j e_ij * v_j ----
    u64 acc2[16];
#pragma unroll
    for (int t = 0; t < 16; ++t) acc2[t] = 0ull;
#pragma unroll 2
    for (int j = 0; j < NN; ++j) {
        float a = Srow[j];
        u64 ap = pack2(a, a);
        const u64* vr = (const u64*)(v_s + j * DD);  // warp-uniform -> broadcast
#pragma unroll
        for (int t = 0; t < 16; ++t) ffma2(acc2[t], ap, vr[t]);
    }
    if (ctx_out) {
        float2* cdst = (float2*)(ctx_out + ((size_t)(b * NN + i)) * CC + g * DD);
#pragma unroll
        for (int t = 0; t < 16; ++t) {
            float lo, hi; unpack2(acc2[t], lo, hi);
            cdst[t] = make_float2(lo * inv, hi * inv);
        }
    }
    __syncthreads();

    // ---- pass 4: coalesced attn write: warp covers consecutive j ----
    if (attn_out) {
        float* adst = attn_out + (size_t)blockIdx.x * (NN * NN);
#pragma unroll 4
        for (int row = 0; row < NN; ++row)
            adst[row * NN + tid] = S[row * NP + tid] * inv_s[row];
    }
}

extern "C" void kernel_launch(void* const* d_in, const int* in_sizes, int n_in,
                              void* d_out, int out_size)
{
    const float* x  = (const float*)d_in[0];
    const float* Wq = (const float*)d_in[1];
    const float* bq = (const float*)d_in[2];
    const float* Wk = (const float*)d_in[3];
    const float* bk = (const float*)d_in[4];

    const size_t ctx_elems  = (size_t)BB * NN * CC;          // 12,582,912
    const size_t attn_elems = (size_t)BB * GG * NN * NN;     // 75,497,472

    float* ctx_ptr  = nullptr;
    float* attn_ptr = nullptr;
    const size_t osz = (size_t)out_size;
    if (osz >= ctx_elems + attn_elems) {          // tuple flattened: ctx then attn
        ctx_ptr  = (float*)d_out;
        attn_ptr = (float*)d_out + ctx_elems;
    } else if (osz == attn_elems) {               // attn only
        attn_ptr = (float*)d_out;
    } else {                                      // ctx only
        ctx_ptr = (float*)d_out;
    }

    constexpr int SMEM_BYTES = (NN * DD * 3 + NN * NP + NN) * 4;  // 222720
    cudaFuncSetAttribute(attn_kernel, cudaFuncAttributeMaxDynamicSharedMemorySize,
                         SMEM_BYTES);

    proj_q_kernel<<<BB * NN / 8, 256>>>(x, Wq, bq);
    proj_k_kernel<<<BB * NN / 8, 256>>>(x, Wk, bk);
    attn_kernel<<<BB * GG, 192, SMEM_BYTES>>>(x, ctx_ptr, attn_ptr);
}

// round 5
// speedup vs baseline: 1.5494x; 1.5462x over previous
#include <cuda_runtime.h>

#define BB 256
#define NN 192
#define CC 256
#define GG 8
#define DD 32

// softmax via exp2: fold SCALE * log2(e) into q
#define CSCALE (0.17677669529663688f * 1.4426950408889634f)

typedef unsigned long long u64;

// scratch (allocation-free rule: __device__ global)
__device__ float g_q[BB * NN * DD];   // 6 MB  [b][n][d], pre-scaled by CSCALE

// ---------- packed f32x2 helpers (sm_100+) ----------
__device__ __forceinline__ u64 pack2(float x, float y) {
    u64 r; asm("mov.b64 %0,{%1,%2};" : "=l"(r) : "f"(x), "f"(y)); return r;
}
__device__ __forceinline__ void unpack2(u64 v, float& x, float& y) {
    asm("mov.b64 {%0,%1},%2;" : "=f"(x), "=f"(y) : "l"(v));
}
__device__ __forceinline__ void ffma2(u64& d, u64 a, u64 b) {
    asm("fma.rn.f32x2 %0,%1,%2,%0;" : "+l"(d) : "l"(a), "l"(b));
}
__device__ __forceinline__ float ex2(float x) {
    float r; asm("ex2.approx.ftz.f32 %0,%1;" : "=f"(r) : "f"(x)); return r;
}

// ============================================================
// proj_q: q[b,n,d] = (sum_c x[b,n,c] * Wq[d,c] + bq[d]) * CSCALE
// Block: 64 rows, 128 threads (4 warps). Warp w: rows [w*16, w*16+16),
// lanes = 32 outputs d. Thread: 16 rows x 1 output, c-paired f32x2.
// Broadcast x loads serve whole warp -> LDS:FFMA2 ~ 17:16 at warp level.
// smem (dynamic): xs2[64][128] u64 (64KB) + Wt2[128][32] u64 (32KB) = 96KB, occ 2.
// ============================================================
__global__ void __launch_bounds__(128, 2) proj_q_kernel(
    const float* __restrict__ x, const float* __restrict__ Wq,
    const float* __restrict__ bq)
{
    extern __shared__ u64 sm_q[];
    u64* xs2 = sm_q;              // [64][128]
    u64* Wt2 = sm_q + 64 * 128;   // [128][32]  Wt2[c2*32+d] = (Wq[d][2c2], Wq[d][2c2+1])

    const int tid = threadIdx.x;
    const int w = tid >> 5, lane = tid & 31;
    const long row0 = (long)blockIdx.x * 64;

    // stage Wq transposed into c-pairs
    for (int idx = tid; idx < DD * CC; idx += 128) {
        int d = idx >> 8, c = idx & 255;
        ((float*)&Wt2[(c >> 1) * 32 + d])[c & 1] = Wq[idx];
    }
    // stage 64 rows of x (float4 coalesced)
    {
        const float4* src = (const float4*)(x + row0 * CC);
        float4* dst = (float4*)xs2;
#pragma unroll
        for (int t = 0; t < 32; ++t) dst[tid + t * 128] = src[tid + t * 128];
    }
    __syncthreads();

    u64 acc[16];
#pragma unroll
    for (int r = 0; r < 16; ++r) acc[r] = 0ull;

    const u64* xbase = xs2 + (w * 16) * 128;
#pragma unroll 2
    for (int c2 = 0; c2 < 128; ++c2) {
        u64 w2 = Wt2[c2 * 32 + lane];
#pragma unroll
        for (int r = 0; r < 16; ++r)
            ffma2(acc[r], xbase[r * 128 + c2], w2);
    }

    const float bias = bq[lane];
#pragma unroll
    for (int r = 0; r < 16; ++r) {
        float lo, hi; unpack2(acc[r], lo, hi);
        g_q[(row0 + w * 16 + r) * DD + lane] = (lo + hi + bias) * CSCALE;
    }
}

// ============================================================
// attn: 1 block per (b,g), 256 threads, occ 1 (228.7KB smem).
// Fuses per-group K projection. S stored TRANSPOSED: ST[j][i], stride 194.
// smem float offsets:
//   qT  [0, 6208)       : [32][194]  q transposed, pre-scaled (from g_q)
//   k_s [6208, 12544)   : [192][33]
//   v_s [12544, 18688)  : [192][32]
//   inv [18688, 18880)
//   wk  [18880, 19904)  : Wk[g] 32x32
//   bk  [19904, 19936)
//   ST  [19936, 57184)  : [192][194]
// ============================================================
#define OFF_QT  0
#define OFF_K   6208
#define OFF_V   12544
#define OFF_INV 18688
#define OFF_WK  18880
#define OFF_BK  19904
#define OFF_ST  19936
#define SM_FLOATS 57184

__global__ void __launch_bounds__(256, 1) attn_kernel(
    const float* __restrict__ x, const float* __restrict__ Wk,
    const float* __restrict__ bk,
    float* __restrict__ ctx_out, float* __restrict__ attn_out)
{
    extern __shared__ float sm[];
    float* qT    = sm + OFF_QT;
    float* k_s   = sm + OFF_K;
    float* v_s   = sm + OFF_V;
    float* inv_s = sm + OFF_INV;
    float* wk_s  = sm + OFF_WK;
    float* bk_s  = sm + OFF_BK;
    float* ST    = sm + OFF_ST;

    const int tid = threadIdx.x;
    const int b = blockIdx.x >> 3;
    const int g = blockIdx.x & 7;

    // ---------------- phase 0: loads ----------------
    // Wk[g] (32x32) + bk[g]
    for (int idx = tid; idx < DD * DD; idx += 256) wk_s[idx] = Wk[g * DD * DD + idx];
    if (tid < DD) bk_s[tid] = bk[g * DD + tid];
    // v = x group slice, float4 coalesced; v_s stride 32
    {
        float4* vdst = (float4*)v_s;
#pragma unroll
        for (int t = 0; t < 6; ++t) {
            int idx = tid + t * 256;                 // 1536 float4
            int n = idx >> 3, f = idx & 7;
            vdst[idx] = ((const float4*)(x + (size_t)(b * NN + n) * CC + g * DD))[f];
        }
    }
    // q transposed (pre-scaled in g_q): qT[d][i], stride 194
    for (int idx = tid; idx < NN * DD; idx += 256) {
        int i = idx >> 5, d = idx & 31;
        qT[d * 194 + i] = g_q[((size_t)b * NN + i) * DD + d];
    }
    __syncthreads();

    // ---------------- phase 0b: fused K projection ----------------
    // k[j][o] = sum_i v[j][i] * Wk[o][i] + bk[o]; k_s stride 33
    if (tid < NN) {
        const int j = tid;
        u64 vr[16];
        const u64* vrow = (const u64*)(v_s + j * DD);
#pragma unroll
        for (int m = 0; m < 16; ++m) vr[m] = vrow[m];
#pragma unroll 4
        for (int o = 0; o < DD; ++o) {
            const u64* wrow = (const u64*)(wk_s + o * DD);  // broadcast
            u64 a0 = 0ull, a1 = 0ull, a2 = 0ull, a3 = 0ull;
#pragma unroll
            for (int m = 0; m < 16; m += 4) {
                ffma2(a0, vr[m    ], wrow[m    ]);
                ffma2(a1, vr[m + 1], wrow[m + 1]);
                ffma2(a2, vr[m + 2], wrow[m + 2]);
                ffma2(a3, vr[m + 3], wrow[m + 3]);
            }
            float l0, h0, l1, h1, l2, h2, l3, h3;
            unpack2(a0, l0, h0); unpack2(a1, l1, h1);
            unpack2(a2, l2, h2); unpack2(a3, l3, h3);
            k_s[j * 33 + o] = (((l0 + h0) + (l1 + h1)) + ((l2 + h2) + (l3 + h3))) + bk_s[o];
        }
    }
    __syncthreads();

    // ---------------- phase 1: ST[j][i] = q'_i . k_j (2D register tile) ----
    // thread: it = tid&15, jt = tid>>4. Tile: 12 j (j = jt+16m) x 12 i
    // (i-pairs i2 = it+16n, n<6). acc paired along i.
    {
        const int it = tid & 15, jt = tid >> 4;
        u64 acc[72];
#pragma unroll
        for (int t = 0; t < 72; ++t) acc[t] = 0ull;

        const u64* qT2 = (const u64*)qT;   // row stride 97 u64
#pragma unroll 2
        for (int d = 0; d < DD; ++d) {
            u64 kk[12];
#pragma unroll
            for (int m = 0; m < 12; ++m) {
                float kv = k_s[(jt + 16 * m) * 33 + d];
                kk[m] = pack2(kv, kv);
            }
            u64 qq[6];
#pragma unroll
            for (int n = 0; n < 6; ++n) qq[n] = qT2[d * 97 + it + 16 * n];
#pragma unroll
            for (int m = 0; m < 12; ++m)
#pragma unroll
                for (int n = 0; n < 6; ++n)
                    ffma2(acc[m * 6 + n], kk[m], qq[n]);
        }
        u64* ST2 = (u64*)ST;               // row stride 97 u64
#pragma unroll
        for (int m = 0; m < 12; ++m)
#pragma unroll
            for (int n = 0; n < 6; ++n)
                ST2[(jt + 16 * m) * 97 + it + 16 * n] = acc[m * 6 + n];
    }
    __syncthreads();

    // ---------------- phase 2: softmax over j per column i ----------------
    if (tid < NN) {
        const int i = tid;
        float m0 = -1e30f, m1 = -1e30f;
#pragma unroll 4
        for (int j = 0; j < NN; j += 2) {
            m0 = fmaxf(m0, ST[j * 194 + i]);
            m1 = fmaxf(m1, ST[(j + 1) * 194 + i]);
        }
        const float m = fmaxf(m0, m1);
        float s0 = 0.f, s1 = 0.f, s2 = 0.f, s3 = 0.f;
#pragma unroll 2
        for (int j = 0; j < NN; j += 4) {
            float e0 = ex2(ST[(j    ) * 194 + i] - m);
            float e1 = ex2(ST[(j + 1) * 194 + i] - m);
            float e2 = ex2(ST[(j + 2) * 194 + i] - m);
            float e3 = ex2(ST[(j + 3) * 194 + i] - m);
            ST[(j    ) * 194 + i] = e0; ST[(j + 1) * 194 + i] = e1;
            ST[(j + 2) * 194 + i] = e2; ST[(j + 3) * 194 + i] = e3;
            s0 += e0; s1 += e1; s2 += e2; s3 += e3;
        }
        inv_s[i] = 1.0f / ((s0 + s1) + (s2 + s3));
    }
    __syncthreads();

    // ---------------- phase 3: ctx = E @ V, tiled (threads 0..191) --------
    // thread: dt = tid&7, rt = tid>>3. Tile: 8 i (pairs i2 = rt*4+pp) x 4 d
    // (d = dt+8dd). acc paired along i (E2 u64 pairs from ST rows).
    if (tid < NN && ctx_out) {
        const int dt = tid & 7, rt = tid >> 3;
        u64 acc[16];
#pragma unroll
        for (int t = 0; t < 16; ++t) acc[t] = 0ull;

        const u64* ST2 = (const u64*)ST;
#pragma unroll 2
        for (int j = 0; j < NN; ++j) {
            u64 e2[4];
#pragma unroll
            for (int pp = 0; pp < 4; ++pp) e2[pp] = ST2[j * 97 + rt * 4 + pp];
            u64 vv[4];
#pragma unroll
            for (int dd = 0; dd < 4; ++dd) {
                float v = v_s[j * DD + dt + 8 * dd];
                vv[dd] = pack2(v, v);
            }
#pragma unroll
            for (int pp = 0; pp < 4; ++pp)
#pragma unroll
                for (int dd = 0; dd < 4; ++dd)
                    ffma2(acc[pp * 4 + dd], e2[pp], vv[dd]);
        }
#pragma unroll
        for (int pp = 0; pp < 4; ++pp) {
            const int i0 = rt * 8 + 2 * pp;
            const float inv0 = inv_s[i0], inv1 = inv_s[i0 + 1];
#pragma unroll
            for (int dd = 0; dd < 4; ++dd) {
                float lo, hi; unpack2(acc[pp * 4 + dd], lo, hi);
                const int d = dt + 8 * dd;
                ctx_out[((size_t)(b * NN + i0    )) * CC + g * DD + d] = lo * inv0;
                ctx_out[((size_t)(b * NN + i0 + 1)) * CC + g * DD + d] = hi * inv1;
            }
        }
    }
    // no sync needed: phase 4 only reads ST/inv_s (ready since phase-2 sync)

    // ---------------- phase 4: attn write (all 8 warps) -------------------
    if (attn_out) {
        const int w = tid >> 5, lane = tid & 31;
        float* adst = attn_out + (size_t)blockIdx.x * (NN * NN);
#pragma unroll 2
        for (int rr = 0; rr < 24; ++rr) {
            const int i = w + 8 * rr;
            const float inv = inv_s[i];
#pragma unroll
            for (int mj = 0; mj < 6; ++mj) {
                const int j = lane + 32 * mj;
                adst[i * NN + j] = ST[j * 194 + i] * inv;
            }
        }
    }
}

extern "C" void kernel_launch(void* const* d_in, const int* in_sizes, int n_in,
                              void* d_out, int out_size)
{
    const float* x  = (const float*)d_in[0];
    const float* Wq = (const float*)d_in[1];
    const float* bq = (const float*)d_in[2];
    const float* Wk = (const float*)d_in[3];
    const float* bk = (const float*)d_in[4];

    const size_t ctx_elems  = (size_t)BB * NN * CC;          // 12,582,912
    const size_t attn_elems = (size_t)BB * GG * NN * NN;     // 75,497,472

    float* ctx_ptr  = nullptr;
    float* attn_ptr = nullptr;
    const size_t osz = (size_t)out_size;
    if (osz >= ctx_elems + attn_elems) {          // tuple flattened: ctx then attn
        ctx_ptr  = (float*)d_out;
        attn_ptr = (float*)d_out + ctx_elems;
    } else if (osz == attn_elems) {               // attn only
        attn_ptr = (float*)d_out;
    } else {                                      // ctx only
        ctx_ptr = (float*)d_out;
    }

    constexpr int SMEM_Q = 96 * 1024;                 // 98304
    constexpr int SMEM_A = SM_FLOATS * 4;             // 228736
    cudaFuncSetAttribute(proj_q_kernel, cudaFuncAttributeMaxDynamicSharedMemorySize, SMEM_Q);
    cudaFuncSetAttribute(attn_kernel,   cudaFuncAttributeMaxDynamicSharedMemorySize, SMEM_A);

    proj_q_kernel<<<BB * NN / 64, 128, SMEM_Q>>>(x, Wq, bq);
    attn_kernel<<<BB * GG, 256, SMEM_A>>>(x, Wk, bk, ctx_ptr, attn_ptr);
}

// round 6
// speedup vs baseline: 1.6602x; 1.0715x over previous
#include <cuda_runtime.h>

#define BB 256
#define NN 192
#define CC 256
#define GG 8
#define DD 32

// softmax via exp2: fold SCALE * log2(e) into q-tilde
#define CSCALE (0.17677669529663688f * 1.4426950408889634f)

typedef unsigned long long u64;

// scratch (allocation-free rule: __device__ global)
// g_qt[b][n][g*32+i2] = CSCALE * (Wk_g^T (x_n Wq^T + bq))[i2]
__device__ float g_qt[BB * NN * CC];   // 50 MB

// ---------- packed f32x2 helpers (sm_100+) ----------
__device__ __forceinline__ u64 pack2(float x, float y) {
    u64 r; asm("mov.b64 %0,{%1,%2};" : "=l"(r) : "f"(x), "f"(y)); return r;
}
__device__ __forceinline__ void unpack2(u64 v, float& x, float& y) {
    asm("mov.b64 {%0,%1},%2;" : "=f"(x), "=f"(y) : "l"(v));
}
__device__ __forceinline__ void ffma2(u64& d, u64 a, u64 b) {
    asm("fma.rn.f32x2 %0,%1,%2,%0;" : "+l"(d) : "l"(a), "l"(b));
}
__device__ __forceinline__ float ex2(float x) {
    float r; asm("ex2.approx.ftz.f32 %0,%1;" : "=f"(r) : "f"(x)); return r;
}

// ============================================================
// proj_qt: phase A: q = (x Wq^T + bq) * CSCALE        (64 rows/block)
//          phase B: qt[c] = sum_o q[o] * Wk[g][o][i2]  (c = g*32+i2)
// 128 threads, smem 96KB (phase B aliases phase A regions), occ 2.
// Note: bk is provably irrelevant (constant-in-j logit shift, cancels
// in softmax), so it is not used anywhere.
// ============================================================
__global__ void __launch_bounds__(128, 2) proj_qt_kernel(
    const float* __restrict__ x, const float* __restrict__ Wq,
    const float* __restrict__ bq, const float* __restrict__ Wk)
{
    extern __shared__ u64 smq[];
    u64* xs2 = smq;            // [64][128] u64 = 64KB (phase A)
    u64* Wt2 = smq + 8192;     // [128][32] u64 = 32KB (phase A)
    float* qs = (float*)smq;   // [64][34] floats (phase B, aliases xs2)
    u64* Wk2  = smq + 8192;    // [8][16][32] u64 = 32KB (phase B, aliases Wt2)

    const int tid = threadIdx.x;
    const int w = tid >> 5, lane = tid & 31;
    const long row0 = (long)blockIdx.x * 64;

    // ---- phase A staging ----
    for (int idx = tid; idx < DD * CC; idx += 128) {
        int d = idx >> 8, c = idx & 255;
        ((float*)&Wt2[(c >> 1) * 32 + d])[c & 1] = Wq[idx];
    }
    {
        const float4* src = (const float4*)(x + row0 * CC);
        float4* dst = (float4*)xs2;
#pragma unroll
        for (int t = 0; t < 32; ++t) dst[tid + t * 128] = src[tid + t * 128];
    }
    __syncthreads();

    // ---- phase A GEMM: thread = (16 rows, 1 d-col), c-paired ----
    float qv[16];
    {
        u64 acc[16];
#pragma unroll
        for (int r = 0; r < 16; ++r) acc[r] = 0ull;
        const u64* xbase = xs2 + (w * 16) * 128;
#pragma unroll 2
        for (int c2 = 0; c2 < 128; ++c2) {
            u64 w2 = Wt2[c2 * 32 + lane];
#pragma unroll
            for (int r = 0; r < 16; ++r)
                ffma2(acc[r], xbase[r * 128 + c2], w2);
        }
        const float bias = bq[lane];
#pragma unroll
        for (int r = 0; r < 16; ++r) {
            float lo, hi; unpack2(acc[r], lo, hi);
            qv[r] = (lo + hi + bias) * CSCALE;
        }
    }
    __syncthreads();   // all phase-A smem reads done before overwrite

    // ---- phase B staging: q rows + paired Wk ----
#pragma unroll
    for (int r = 0; r < 16; ++r) qs[(w * 16 + r) * 34 + lane] = qv[r];
    for (int idx = tid; idx < GG * 16 * 32; idx += 128) {
        int g = idx >> 9, o2 = (idx >> 5) & 15, i2 = idx & 31;
        Wk2[idx] = pack2(Wk[(g * 32 + 2 * o2) * 32 + i2],
                         Wk[(g * 32 + 2 * o2 + 1) * 32 + i2]);
    }
    __syncthreads();

    // ---- phase B GEMM: thread = cols (tid, tid+128), rows in 8-chunks ----
    {
        const int c0 = tid, c1 = tid + 128;
        const u64* wk0 = Wk2 + (c0 >> 5) * 512 + (c0 & 31);
        const u64* wk1 = Wk2 + (c1 >> 5) * 512 + (c1 & 31);
        const u64* qs2 = (const u64*)qs;   // row stride 17 u64
#pragma unroll 1
        for (int ch = 0; ch < 8; ++ch) {
            u64 a0[8], a1[8];
#pragma unroll
            for (int r = 0; r < 8; ++r) { a0[r] = 0ull; a1[r] = 0ull; }
#pragma unroll
            for (int o2 = 0; o2 < 16; ++o2) {
                u64 w0 = wk0[o2 * 32], w1 = wk1[o2 * 32];
#pragma unroll
                for (int r = 0; r < 8; ++r) {
                    u64 q2 = qs2[(ch * 8 + r) * 17 + o2];  // broadcast
                    ffma2(a0[r], q2, w0);
                    ffma2(a1[r], q2, w1);
                }
            }
#pragma unroll
            for (int r = 0; r < 8; ++r) {
                float l0, h0, l1, h1;
                unpack2(a0[r], l0, h0); unpack2(a1[r], l1, h1);
                const long row = row0 + ch * 8 + r;
                g_qt[row * CC + c0] = l0 + h0;
                g_qt[row * CC + c1] = l1 + h1;
            }
        }
    }
}

// ============================================================
// attn: 1 block per (b,g,i-tile of 96); 256 threads; occ 2 (112.4KB smem).
// S = qt^T x_g ; softmax over j; ctx = P V; attn written directly.
// smem float offsets:
//   qT [0, 3136)      : [32][98]   q-tilde transposed for this i-tile
//   v  [3136, 9472)   : [192][33]  x group slice (padded stride 33)
//   ST [9472, 28288)  : [192][98]  S transposed [j][i]
//   pm [28288, 28480) : [2][96] partial max
//   ps [28480, 28672) : [2][96] partial sum
//   inv[28672, 28768)
// ============================================================
#define OFF_V   3136
#define OFF_ST  9472
#define OFF_PM  28288
#define OFF_PS  28480
#define OFF_INV 28672
#define SM_FLOATS 28768

__global__ void __launch_bounds__(256, 2) attn_kernel(
    const float* __restrict__ x,
    float* __restrict__ ctx_out, float* __restrict__ attn_out)
{
    extern __shared__ float sm[];
    float* qT    = sm;
    float* v_s   = sm + OFF_V;
    float* ST    = sm + OFF_ST;
    float* pm    = sm + OFF_PM;
    float* ps    = sm + OFF_PS;
    float* inv_s = sm + OFF_INV;

    const int tid = threadIdx.x;
    const int bg = blockIdx.x >> 1;        // b*8+g
    const int b = bg >> 3, g = bg & 7;
    const int i0 = (blockIdx.x & 1) * 96;

    // ---------------- P0: stage qT (transposed) and v ----------------
    for (int idx = tid; idx < 96 * DD; idx += 256) {          // 3072
        int i = idx >> 5, d = idx & 31;
        qT[d * 98 + i] = g_qt[((size_t)(b * NN) + i0 + i) * CC + g * DD + d];
    }
    for (int idx = tid; idx < NN * DD; idx += 256) {          // 6144
        int n = idx >> 5, d = idx & 31;
        v_s[n * 33 + d] = x[((size_t)(b * NN) + n) * CC + g * DD + d];
    }
    __syncthreads();

    // ---------------- P1: ST[j][i] = sum_d qT[d][i] * v[j][d] ----------
    // thread: it = tid&7 (i2 = it+8n, n<6), jt = tid>>3 (j = jt+32m, m<6)
    {
        const int it = tid & 7, jt = tid >> 3;
        u64 acc[36];
#pragma unroll
        for (int t = 0; t < 36; ++t) acc[t] = 0ull;
        const u64* qT2 = (const u64*)qT;          // row stride 49 u64
#pragma unroll 2
        for (int d = 0; d < DD; ++d) {
            u64 vv[6], qq[6];
#pragma unroll
            for (int m = 0; m < 6; ++m) {
                float v = v_s[(jt + 32 * m) * 33 + d];
                vv[m] = pack2(v, v);
            }
#pragma unroll
            for (int n = 0; n < 6; ++n) qq[n] = qT2[d * 49 + it + 8 * n];
#pragma unroll
            for (int m = 0; m < 6; ++m)
#pragma unroll
                for (int n = 0; n < 6; ++n)
                    ffma2(acc[m * 6 + n], vv[m], qq[n]);
        }
        u64* ST2 = (u64*)ST;                      // row stride 49 u64
#pragma unroll
        for (int m = 0; m < 6; ++m)
#pragma unroll
            for (int n = 0; n < 6; ++n)
                ST2[(jt + 32 * m) * 49 + it + 8 * n] = acc[m * 6 + n];
    }
    __syncthreads();

    // ---------------- P2: softmax over j (2-way split over j) ----------
    if (tid < 192) {
        const int i = tid % 96, h = tid / 96, j0 = h * 96;
        float m0 = -1e30f, m1 = -1e30f, m2 = -1e30f, m3 = -1e30f;
#pragma unroll 2
        for (int j = 0; j < 96; j += 4) {
            m0 = fmaxf(m0, ST[(j0 + j    ) * 98 + i]);
            m1 = fmaxf(m1, ST[(j0 + j + 1) * 98 + i]);
            m2 = fmaxf(m2, ST[(j0 + j + 2) * 98 + i]);
            m3 = fmaxf(m3, ST[(j0 + j + 3) * 98 + i]);
        }
        pm[h * 96 + i] = fmaxf(fmaxf(m0, m1), fmaxf(m2, m3));
    }
    __syncthreads();
    if (tid < 192) {
        const int i = tid % 96, h = tid / 96, j0 = h * 96;
        const float m = fmaxf(pm[i], pm[96 + i]);
        float s0 = 0.f, s1 = 0.f, s2 = 0.f, s3 = 0.f;
#pragma unroll 2
        for (int j = 0; j < 96; j += 4) {
            float e0 = ex2(ST[(j0 + j    ) * 98 + i] - m);
            float e1 = ex2(ST[(j0 + j + 1) * 98 + i] - m);
            float e2 = ex2(ST[(j0 + j + 2) * 98 + i] - m);
            float e3 = ex2(ST[(j0 + j + 3) * 98 + i] - m);
            ST[(j0 + j    ) * 98 + i] = e0; ST[(j0 + j + 1) * 98 + i] = e1;
            ST[(j0 + j + 2) * 98 + i] = e2; ST[(j0 + j + 3) * 98 + i] = e3;
            s0 += e0; s1 += e1; s2 += e2; s3 += e3;
        }
        ps[h * 96 + i] = (s0 + s1) + (s2 + s3);
    }
    __syncthreads();
    if (tid < 96) inv_s[tid] = 1.0f / (ps[tid] + ps[96 + tid]);
    __syncthreads();

    // ---------------- P3: ctx = E @ V (threads 0..191) -----------------
    // thread: dt = tid&7 (d = dt+8dd), i2g = tid>>3 (i-pairs i2g, i2g+24)
    if (ctx_out && tid < 192) {
        const int dt = tid & 7, i2g = tid >> 3;
        u64 acc[8];
#pragma unroll
        for (int t = 0; t < 8; ++t) acc[t] = 0ull;
        const u64* ST2 = (const u64*)ST;
#pragma unroll 2
        for (int j = 0; j < NN; ++j) {
            u64 e0 = ST2[j * 49 + i2g];
            u64 e1 = ST2[j * 49 + i2g + 24];
            const float* vr = v_s + j * 33 + dt;
#pragma unroll
            for (int dd = 0; dd < 4; ++dd) {
                float v = vr[8 * dd];
                u64 vv = pack2(v, v);
                ffma2(acc[dd],     e0, vv);
                ffma2(acc[4 + dd], e1, vv);
            }
        }
#pragma unroll
        for (int p = 0; p < 2; ++p) {
            const int i2 = i2g + 24 * p;
            const float ia = inv_s[2 * i2], ib = inv_s[2 * i2 + 1];
#pragma unroll
            for (int dd = 0; dd < 4; ++dd) {
                float lo, hi; unpack2(acc[p * 4 + dd], lo, hi);
                const int d = dt + 8 * dd;
                ctx_out[((size_t)(b * NN) + i0 + 2 * i2    ) * CC + g * DD + d] = lo * ia;
                ctx_out[((size_t)(b * NN) + i0 + 2 * i2 + 1) * CC + g * DD + d] = hi * ib;
            }
        }
    }
    // P3/P4 both read-only on ST/inv after the P2 sync; no extra sync.

    // ---------------- P4: attn write (all 8 warps, coalesced) ----------
    if (attn_out) {
        const int w2 = tid >> 5, lane = tid & 31;
        float* adst = attn_out + ((size_t)bg * NN + i0) * NN;
#pragma unroll 2
        for (int rr = 0; rr < 12; ++rr) {
            const int i = w2 + 8 * rr;
            const float inv = inv_s[i];
#pragma unroll
            for (int mj = 0; mj < 6; ++mj) {
                const int j = lane + 32 * mj;
                adst[(size_t)i * NN + j] = ST[j * 98 + i] * inv;
            }
        }
    }
}

extern "C" void kernel_launch(void* const* d_in, const int* in_sizes, int n_in,
                              void* d_out, int out_size)
{
    const float* x  = (const float*)d_in[0];
    const float* Wq = (const float*)d_in[1];
    const float* bq = (const float*)d_in[2];
    const float* Wk = (const float*)d_in[3];
    // d_in[4] = bk: provably no effect on outputs (cancels in softmax)

    const size_t ctx_elems  = (size_t)BB * NN * CC;          // 12,582,912
    const size_t attn_elems = (size_t)BB * GG * NN * NN;     // 75,497,472

    float* ctx_ptr  = nullptr;
    float* attn_ptr = nullptr;
    const size_t osz = (size_t)out_size;
    if (osz >= ctx_elems + attn_elems) {          // tuple flattened: ctx then attn
        ctx_ptr  = (float*)d_out;
        attn_ptr = (float*)d_out + ctx_elems;
    } else if (osz == attn_elems) {               // attn only
        attn_ptr = (float*)d_out;
    } else {                                      // ctx only
        ctx_ptr = (float*)d_out;
    }

    constexpr int SMEM_P = 96 * 1024;             // 98304
    constexpr int SMEM_A = SM_FLOATS * 4;         // 115072 -> occ 2
    cudaFuncSetAttribute(proj_qt_kernel, cudaFuncAttributeMaxDynamicSharedMemorySize, SMEM_P);
    cudaFuncSetAttribute(attn_kernel,    cudaFuncAttributeMaxDynamicSharedMemorySize, SMEM_A);

    proj_qt_kernel<<<BB * NN / 64, 128, SMEM_P>>>(x, Wq, bq, Wk);
    attn_kernel<<<BB * GG * 2, 256, SMEM_A>>>(x, ctx_ptr, attn_ptr);
}

// round 7
// speedup vs baseline: 1.9408x; 1.1690x over previous
#include <cuda_runtime.h>

#define BB 256
#define NN 192
#define CC 256
#define GG 8
#define DD 32

// softmax via exp2: fold SCALE * log2(e) into q-tilde
#define CSCALE (0.17677669529663688f * 1.4426950408889634f)

typedef unsigned long long u64;

// scratch (allocation-free rule: __device__ global)
// g_qt[b][n][g*32+i2] = CSCALE * (Wk_g^T (x_n Wq^T + bq))[i2]
__device__ float g_qt[BB * NN * CC];   // 50 MB

// ---------- packed f32x2 helpers (sm_100+) ----------
__device__ __forceinline__ u64 pack2(float x, float y) {
    u64 r; asm("mov.b64 %0,{%1,%2};" : "=l"(r) : "f"(x), "f"(y)); return r;
}
__device__ __forceinline__ void unpack2(u64 v, float& x, float& y) {
    asm("mov.b64 {%0,%1},%2;" : "=f"(x), "=f"(y) : "l"(v));
}
__device__ __forceinline__ void ffma2(u64& d, u64 a, u64 b) {
    asm("fma.rn.f32x2 %0,%1,%2,%0;" : "+l"(d) : "l"(a), "l"(b));
}
__device__ __forceinline__ float ex2(float x) {
    float r; asm("ex2.approx.ftz.f32 %0,%1;" : "=f"(r) : "f"(x)); return r;
}

// ============================================================
// proj_qt: phase A: q = (x Wq^T + bq) * CSCALE         (32 rows/block)
//          phase B: qt[c] = sum_o q[o] * Wk[g][o][i2]  (c = g*32+i2)
// 128 threads, smem 64KB -> occ 3 (12 warps/SM).
// bk is provably irrelevant (constant-in-j logit shift, cancels in softmax).
// ============================================================
__global__ void __launch_bounds__(128, 3) proj_qt_kernel(
    const float* __restrict__ x, const float* __restrict__ Wq,
    const float* __restrict__ bq, const float* __restrict__ Wk)
{
    extern __shared__ u64 smq[];
    u64* xs2 = smq;            // [32][128] u64 = 32KB (phase A)
    u64* Wt2 = smq + 4096;     // [128][32] u64 = 32KB (phase A)
    float* qs = (float*)smq;   // [32][34] floats (phase B, aliases xs2)
    u64* Wk2  = smq + 4096;    // [8][16][32] u64 = 32KB (phase B, aliases Wt2)

    const int tid = threadIdx.x;
    const int w = tid >> 5, lane = tid & 31;
    const long row0 = (long)blockIdx.x * 32;

    // ---- phase A staging ----
    for (int idx = tid; idx < DD * CC; idx += 128) {
        int d = idx >> 8, c = idx & 255;
        ((float*)&Wt2[(c >> 1) * 32 + d])[c & 1] = Wq[idx];
    }
    {
        const float4* src = (const float4*)(x + row0 * CC);
        float4* dst = (float4*)xs2;
#pragma unroll
        for (int t = 0; t < 16; ++t) dst[tid + t * 128] = src[tid + t * 128];
    }
    __syncthreads();

    // ---- phase A GEMM: warp w -> rows [w*8, w*8+8), lane = d ----
    float qv[8];
    {
        u64 acc[8];
#pragma unroll
        for (int r = 0; r < 8; ++r) acc[r] = 0ull;
        const u64* xbase = xs2 + (w * 8) * 128;
#pragma unroll 4
        for (int c2 = 0; c2 < 128; ++c2) {
            u64 w2 = Wt2[c2 * 32 + lane];
#pragma unroll
            for (int r = 0; r < 8; ++r)
                ffma2(acc[r], xbase[r * 128 + c2], w2);
        }
        const float bias = bq[lane];
#pragma unroll
        for (int r = 0; r < 8; ++r) {
            float lo, hi; unpack2(acc[r], lo, hi);
            qv[r] = (lo + hi + bias) * CSCALE;
        }
    }
    __syncthreads();   // all phase-A smem reads done before aliased overwrite

    // ---- phase B staging: q rows + paired Wk ----
#pragma unroll
    for (int r = 0; r < 8; ++r) qs[(w * 8 + r) * 34 + lane] = qv[r];
    for (int idx = tid; idx < GG * 16 * 32; idx += 128) {
        int g = idx >> 9, o2 = (idx >> 5) & 15, i2 = idx & 31;
        Wk2[idx] = pack2(Wk[(g * 32 + 2 * o2) * 32 + i2],
                         Wk[(g * 32 + 2 * o2 + 1) * 32 + i2]);
    }
    __syncthreads();

    // ---- phase B GEMM: thread = cols (tid, tid+128), rows in 8-chunks ----
    {
        const int c0 = tid, c1 = tid + 128;
        const u64* wk0 = Wk2 + (c0 >> 5) * 512 + (c0 & 31);
        const u64* wk1 = Wk2 + (c1 >> 5) * 512 + (c1 & 31);
        const u64* qs2 = (const u64*)qs;   // row stride 17 u64
#pragma unroll 1
        for (int ch = 0; ch < 4; ++ch) {
            u64 a0[8], a1[8];
#pragma unroll
            for (int r = 0; r < 8; ++r) { a0[r] = 0ull; a1[r] = 0ull; }
#pragma unroll
            for (int o2 = 0; o2 < 16; ++o2) {
                u64 w0 = wk0[o2 * 32], w1 = wk1[o2 * 32];
#pragma unroll
                for (int r = 0; r < 8; ++r) {
                    u64 q2 = qs2[(ch * 8 + r) * 17 + o2];  // broadcast
                    ffma2(a0[r], q2, w0);
                    ffma2(a1[r], q2, w1);
                }
            }
#pragma unroll
            for (int r = 0; r < 8; ++r) {
                float l0, h0, l1, h1;
                unpack2(a0[r], l0, h0); unpack2(a1[r], l1, h1);
                const long row = row0 + ch * 8 + r;
                g_qt[row * CC + c0] = l0 + h0;
                g_qt[row * CC + c1] = l1 + h1;
            }
        }
    }
}

// ============================================================
// attn: 1 block per (b,g,i-half of 96); 256 threads; occ 2 (113.2KB).
// i-MAJOR S layout + transposed V:
//   q_s [96][36]  @ 0      (3456 floats)  q-tilde rows (i-major)
//   vT  [32][194] @ 3456   (6208 floats)  x group slice transposed [d][j]
//   ST  [96][194] @ 9664   (18624 floats) S then p=softmax, i-major
// P1: S = q vT (tile 6i x 6j2, pairs along j)
// P2: warp-per-row softmax (shuffle reduce) + FUSED attn gmem write
// P3: ctx = P V: scalar acc, BOTH operands u64-paired along j (tile 3i x 4d)
// ============================================================
#define OFF_VT  3456
#define OFF_ST  9664
#define SM_FLOATS 28288

__global__ void __launch_bounds__(256, 2) attn_kernel(
    const float* __restrict__ x,
    float* __restrict__ ctx_out, float* __restrict__ attn_out)
{
    extern __shared__ float sm[];
    float* q_s = sm;
    float* vT  = sm + OFF_VT;
    float* ST  = sm + OFF_ST;

    const int tid = threadIdx.x;
    const int bg = blockIdx.x >> 1;        // b*8+g
    const int b = bg >> 3, g = bg & 7;
    const int i0 = (blockIdx.x & 1) * 96;

    // ---------------- P0: stage q_s (row-major) and vT (transposed) ------
#pragma unroll
    for (int t = 0; t < 3; ++t) {          // 768 float4
        int idx = tid + t * 256;
        int i = idx >> 3, f = idx & 7;
        ((float4*)(q_s + i * 36))[f] =
            ((const float4*)(g_qt + ((size_t)(b * NN) + i0 + i) * CC + g * DD))[f];
    }
#pragma unroll
    for (int t = 0; t < 6; ++t) {          // 1536 float4, coalesced read, scatter write
        int idx = tid + t * 256;
        int n = idx >> 3, f = idx & 7;
        float4 v4 = ((const float4*)(x + ((size_t)(b * NN) + n) * CC + g * DD))[f];
        vT[(4 * f    ) * 194 + n] = v4.x;
        vT[(4 * f + 1) * 194 + n] = v4.y;
        vT[(4 * f + 2) * 194 + n] = v4.z;
        vT[(4 * f + 3) * 194 + n] = v4.w;
    }
    __syncthreads();

    // ---------------- P1: ST[i][j] = sum_d q_s[i][d] * vT[d][j] ----------
    // thread: jq = tid&15 (j2 = jq+16n, n<6), iq = tid>>4 (i = iq+16m, m<6)
    {
        const int jq = tid & 15, iq = tid >> 4;
        u64 acc[36];
#pragma unroll
        for (int t = 0; t < 36; ++t) acc[t] = 0ull;
        const u64* vT2 = (const u64*)vT;          // row stride 97 u64
#pragma unroll 2
        for (int d = 0; d < DD; ++d) {
            u64 qq[6], vv[6];
#pragma unroll
            for (int m = 0; m < 6; ++m) {
                float q = q_s[(iq + 16 * m) * 36 + d];   // broadcast
                qq[m] = pack2(q, q);
            }
#pragma unroll
            for (int n = 0; n < 6; ++n) vv[n] = vT2[d * 97 + jq + 16 * n];
#pragma unroll
            for (int m = 0; m < 6; ++m)
#pragma unroll
                for (int n = 0; n < 6; ++n)
                    ffma2(acc[m * 6 + n], qq[m], vv[n]);
        }
        u64* ST2 = (u64*)ST;                      // row stride 97 u64
#pragma unroll
        for (int m = 0; m < 6; ++m)
#pragma unroll
            for (int n = 0; n < 6; ++n)
                ST2[(iq + 16 * m) * 97 + jq + 16 * n] = acc[m * 6 + n];
    }
    __syncthreads();

    // ---------------- P2: warp-per-row softmax + fused attn write --------
    {
        const int w2 = tid >> 5, lane = tid & 31;
        float* adst = attn_out ? attn_out + ((size_t)bg * NN + i0) * NN : nullptr;
#pragma unroll 1
        for (int r = 0; r < 12; ++r) {
            const int i = w2 + 8 * r;
            float* srow = ST + i * 194;
            float s[6];
#pragma unroll
            for (int m = 0; m < 6; ++m) s[m] = srow[lane + 32 * m];
            float mx = fmaxf(fmaxf(fmaxf(s[0], s[1]), fmaxf(s[2], s[3])),
                             fmaxf(s[4], s[5]));
#pragma unroll
            for (int o = 16; o > 0; o >>= 1)
                mx = fmaxf(mx, __shfl_xor_sync(0xffffffffu, mx, o));
            float p[6], sum = 0.f;
#pragma unroll
            for (int m = 0; m < 6; ++m) { p[m] = ex2(s[m] - mx); sum += p[m]; }
#pragma unroll
            for (int o = 16; o > 0; o >>= 1)
                sum += __shfl_xor_sync(0xffffffffu, sum, o);
            const float inv = 1.0f / sum;
#pragma unroll
            for (int m = 0; m < 6; ++m) {
                p[m] *= inv;
                srow[lane + 32 * m] = p[m];            // ST now holds p
            }
            if (adst) {
#pragma unroll
                for (int m = 0; m < 6; ++m)
                    adst[(size_t)i * NN + lane + 32 * m] = p[m];  // coalesced
            }
        }
    }
    __syncthreads();

    // ---------------- P3: ctx[i][d] = sum_j p[i][j] * v[j][d] ------------
    // thread: dg = tid&7 (d = dg+8dd, dd<4), ig = tid>>3 (i = 3ig+a, a<3)
    // both operands u64-paired along j -> scalar result lo+hi.
    if (ctx_out) {
        const int dg = tid & 7, ig = tid >> 3;
        u64 acc[12];
#pragma unroll
        for (int t = 0; t < 12; ++t) acc[t] = 0ull;
        const u64* ST2 = (const u64*)ST;
        const u64* vT2 = (const u64*)vT;
#pragma unroll 2
        for (int j2 = 0; j2 < 96; ++j2) {
            u64 e2[3], v2[4];
#pragma unroll
            for (int a = 0; a < 3; ++a) e2[a] = ST2[(3 * ig + a) * 97 + j2];
#pragma unroll
            for (int dd = 0; dd < 4; ++dd) v2[dd] = vT2[(dg + 8 * dd) * 97 + j2];
#pragma unroll
            for (int a = 0; a < 3; ++a)
#pragma unroll
                for (int dd = 0; dd < 4; ++dd)
                    ffma2(acc[a * 4 + dd], e2[a], v2[dd]);
        }
#pragma unroll
        for (int a = 0; a < 3; ++a) {
            const size_t row = (size_t)(b * NN) + i0 + 3 * ig + a;
#pragma unroll
            for (int dd = 0; dd < 4; ++dd) {
                float lo, hi; unpack2(acc[a * 4 + dd], lo, hi);
                ctx_out[row * CC + g * DD + dg + 8 * dd] = lo + hi;
            }
        }
    }
}

extern "C" void kernel_launch(void* const* d_in, const int* in_sizes, int n_in,
                              void* d_out, int out_size)
{
    const float* x  = (const float*)d_in[0];
    const float* Wq = (const float*)d_in[1];
    const float* bq = (const float*)d_in[2];
    const float* Wk = (const float*)d_in[3];
    // d_in[4] = bk: provably no effect on outputs (cancels in softmax)

    const size_t ctx_elems  = (size_t)BB * NN * CC;          // 12,582,912
    const size_t attn_elems = (size_t)BB * GG * NN * NN;     // 75,497,472

    float* ctx_ptr  = nullptr;
    float* attn_ptr = nullptr;
    const size_t osz = (size_t)out_size;
    if (osz >= ctx_elems + attn_elems) {          // tuple flattened: ctx then attn
        ctx_ptr  = (float*)d_out;
        attn_ptr = (float*)d_out + ctx_elems;
    } else if (osz == attn_elems) {               // attn only
        attn_ptr = (float*)d_out;
    } else {                                      // ctx only
        ctx_ptr = (float*)d_out;
    }

    constexpr int SMEM_P = 64 * 1024;             // 65536 -> occ 3
    constexpr int SMEM_A = SM_FLOATS * 4;         // 113152 -> occ 2
    cudaFuncSetAttribute(proj_qt_kernel, cudaFuncAttributeMaxDynamicSharedMemorySize, SMEM_P);
    cudaFuncSetAttribute(attn_kernel,    cudaFuncAttributeMaxDynamicSharedMemorySize, SMEM_A);

    proj_qt_kernel<<<BB * NN / 32, 128, SMEM_P>>>(x, Wq, bq, Wk);
    attn_kernel<<<BB * GG * 2, 256, SMEM_A>>>(x, ctx_ptr, attn_ptr);
}